// round 4
// baseline (speedup 1.0000x reference)
#include <cuda_runtime.h>
#include <math.h>

// Problem dims
#define B 8
#define S 4096
#define F 128
#define T 16
#define THRESH 0.1f
#define EPS 1e-8f

#define NCHUNK 32            // s-chunks for the stats pass (128 rows each)
#define RUN 16               // consecutive s-rows per thread in k_acc

// Scratch: per-chunk partial sums (deterministic writes, no zero/atomic) + inv-std
__device__ float g_p1[NCHUNK][B * F];
__device__ float g_p2[NCHUNK][B * F];
__device__ __align__(16) float g_inv[B * F];

// Stats pass: float4 over f (32 groups), 8 s-threads per block, each thread
// rolls prev in registers across RUN consecutive rows. grid (NCHUNK, B) = 256
// blocks of 256 threads. No atomics, no fences (R3 lesson: device-wide
// __threadfence cost ~40us).
__global__ void k_acc(const float4* __restrict__ x) {
    int f4 = threadIdx.x;     // 0..31  (f = f4*4..f4*4+3)
    int ty = threadIdx.y;     // 0..7
    int chunk = blockIdx.x;   // 0..NCHUNK-1
    int b = blockIdx.y;

    const float4* base = x + (size_t)b * S * 32;   // rows of 32 float4
    int s_start = chunk * (8 * RUN) + ty * RUN;

    // prepend semantics: diff[0] = 0
    float4 prev = (s_start == 0) ? base[f4]
                                 : base[(size_t)(s_start - 1) * 32 + f4];

    float4 s1 = make_float4(0.f, 0.f, 0.f, 0.f);
    float4 s2 = make_float4(0.f, 0.f, 0.f, 0.f);
    #pragma unroll
    for (int j = 0; j < RUN; j++) {
        float4 cur = base[(size_t)(s_start + j) * 32 + f4];
        float dx = cur.x - prev.x, dy = cur.y - prev.y;
        float dz = cur.z - prev.z, dw = cur.w - prev.w;
        s1.x += dx; s1.y += dy; s1.z += dz; s1.w += dw;
        s2.x += dx * dx; s2.y += dy * dy; s2.z += dz * dz; s2.w += dw * dw;
        prev = cur;
    }

    __shared__ float4 sh1[8][32];
    __shared__ float4 sh2[8][32];
    sh1[ty][f4] = s1;
    sh2[ty][f4] = s2;
    __syncthreads();
    if (ty == 0) {
        float4 t1 = make_float4(0.f, 0.f, 0.f, 0.f);
        float4 t2 = make_float4(0.f, 0.f, 0.f, 0.f);
        #pragma unroll
        for (int j = 0; j < 8; j++) {
            float4 a = sh1[j][f4], c = sh2[j][f4];
            t1.x += a.x; t1.y += a.y; t1.z += a.z; t1.w += a.w;
            t2.x += c.x; t2.y += c.y; t2.z += c.z; t2.w += c.w;
        }
        *reinterpret_cast<float4*>(&g_p1[chunk][b * F + f4 * 4]) = t1;
        *reinterpret_cast<float4*>(&g_p2[chunk][b * F + f4 * 4]) = t2;
    }
}

__global__ void k_inv() {
    int i = blockIdx.x * blockDim.x + threadIdx.x;
    if (i < B * F) {
        double sum = 0.0, sumsq = 0.0;
        #pragma unroll
        for (int c = 0; c < NCHUNK; c++) {
            sum   += (double)g_p1[c][i];
            sumsq += (double)g_p2[c][i];
        }
        double m = sum / (double)S;
        double var = sumsq / (double)S - m * m;
        if (var < 0.0) var = 0.0;
        float sd = (float)sqrt(var);
        g_inv[i] = 1.0f / (sd + EPS);
    }
}

// Main expansion: one float4 per thread over B*S*F/4 elements.
// 16 coalesced plain float4 stores per thread (phase pattern t%3).
__global__ void k_main(const float4* __restrict__ x, float4* __restrict__ out) {
    int i = blockIdx.x * blockDim.x + threadIdx.x;  // 0 .. B*S*(F/4)-1
    int f4 = i & 31;            // F/4 = 32
    int s  = (i >> 5) & 4095;
    int b  = i >> 17;

    float4 cur = x[i];
    float4 prv = (s == 0) ? cur : x[i - 32];

    const float4 inv4 = *reinterpret_cast<const float4*>(&g_inv[b * F + f4 * 4]);

    float ndx = (cur.x - prv.x) * inv4.x;
    float ndy = (cur.y - prv.y) * inv4.y;
    float ndz = (cur.z - prv.z) * inv4.z;
    float ndw = (cur.w - prv.w) * inv4.w;

    float4 pos, neg;
    const float4 zero = make_float4(0.f, 0.f, 0.f, 0.f);
    pos.x = (ndx >=  THRESH) ? 1.f : 0.f;
    pos.y = (ndy >=  THRESH) ? 1.f : 0.f;
    pos.z = (ndz >=  THRESH) ? 1.f : 0.f;
    pos.w = (ndw >=  THRESH) ? 1.f : 0.f;
    neg.x = (-ndx >= THRESH) ? 1.f : 0.f;
    neg.y = (-ndy >= THRESH) ? 1.f : 0.f;
    neg.z = (-ndz >= THRESH) ? 1.f : 0.f;
    neg.w = (-ndw >= THRESH) ? 1.f : 0.f;

    // out index (b,t,s,f4) = ((b*T + t)*S + s)*32 + f4
    const size_t tstride = (size_t)S * 32;
    size_t obase = ((size_t)b * T * S + s) * 32 + f4;

    #pragma unroll
    for (int t = 0; t < T; t++) {
        int ph = t % 3;
        out[obase + (size_t)t * tstride] = (ph == 0) ? pos : (ph == 1) ? neg : zero;
    }
}

extern "C" void kernel_launch(void* const* d_in, const int* in_sizes, int n_in,
                              void* d_out, int out_size) {
    const float* x = (const float*)d_in[0];
    float* out = (float*)d_out;

    dim3 bt(32, 8);
    dim3 gr(NCHUNK, B);
    k_acc<<<gr, bt>>>((const float4*)x);
    k_inv<<<1, 1024>>>();

    int n4 = B * S * (F / 4);          // 1,048,576 float4 threads
    k_main<<<n4 / 256, 256>>>((const float4*)x, (float4*)out);
}

// round 6
// speedup vs baseline: 1.5631x; 1.5631x over previous
#include <cuda_runtime.h>
#include <math.h>

// Problem dims
#define B 8
#define S 4096
#define F 128
#define T 16
#define THRESH 0.1f
#define EPS 1e-8f

// Scratch: per-(b,f) accumulators and inverse-std (1024 entries).
// Zero-initialized at module load; k_inv re-zeros them after use so every
// kernel_launch call (incl. graph replays) sees clean accumulators.
__device__ double g_sum[B * F];
__device__ double g_sumsq[B * F];
__device__ __align__(16) float g_inv[B * F];

// Accumulate sum / sumsq of diff along S for each (b,f).
// grid (32 s-chunks, B), block (128 f, 8 s-threads). Coalesced loads.
// (R1-measured configuration — part of the 60.1us end-to-end best.)
__global__ void k_acc(const float* __restrict__ x) {
    int f = threadIdx.x;         // 0..127
    int ty = threadIdx.y;        // 0..7
    int chunk = blockIdx.x;      // 0..31 (128 s each)
    int b = blockIdx.y;

    const float* base = x + (size_t)b * S * F;
    int s0 = chunk * 128;

    float s1 = 0.f, s2 = 0.f;
    #pragma unroll 4
    for (int i = ty; i < 128; i += 8) {
        int s = s0 + i;
        float cur = base[(size_t)s * F + f];
        float prv = (s == 0) ? cur : base[(size_t)(s - 1) * F + f];
        float d = cur - prv;
        s1 += d;
        s2 += d * d;
    }

    __shared__ float sh[8][128];
    sh[ty][f] = s1;
    __syncthreads();
    if (ty == 0) {
        float t = 0.f;
        #pragma unroll
        for (int j = 0; j < 8; j++) t += sh[j][f];
        atomicAdd(&g_sum[b * F + f], (double)t);
    }
    __syncthreads();
    sh[ty][f] = s2;
    __syncthreads();
    if (ty == 0) {
        float t = 0.f;
        #pragma unroll
        for (int j = 0; j < 8; j++) t += sh[j][f];
        atomicAdd(&g_sumsq[b * F + f], (double)t);
    }
}

__global__ void k_inv() {
    int i = blockIdx.x * blockDim.x + threadIdx.x;
    if (i < B * F) {
        double m = g_sum[i] / (double)S;
        double var = g_sumsq[i] / (double)S - m * m;
        if (var < 0.0) var = 0.0;
        float sd = (float)sqrt(var);
        g_inv[i] = 1.0f / (sd + EPS);
        // Re-zero accumulators for the next kernel_launch call / graph replay.
        g_sum[i] = 0.0;
        g_sumsq[i] = 0.0;
    }
}

// Main expansion: one float4 per thread over B*S*F/4 elements.
// 16 coalesced plain float4 stores per thread (phase pattern t%3).
// (R1-measured: 45.2us, DRAM 63%, the practical write-BW wall.)
__global__ void k_main(const float4* __restrict__ x, float4* __restrict__ out) {
    int i = blockIdx.x * blockDim.x + threadIdx.x;  // 0 .. B*S*(F/4)-1
    int f4 = i & 31;            // F/4 = 32
    int s  = (i >> 5) & 4095;
    int b  = i >> 17;

    float4 cur = x[i];
    float4 prv = (s == 0) ? cur : x[i - 32];

    const float4 inv4 = *reinterpret_cast<const float4*>(&g_inv[b * F + f4 * 4]);

    float ndx = (cur.x - prv.x) * inv4.x;
    float ndy = (cur.y - prv.y) * inv4.y;
    float ndz = (cur.z - prv.z) * inv4.z;
    float ndw = (cur.w - prv.w) * inv4.w;

    float4 pos, neg;
    const float4 zero = make_float4(0.f, 0.f, 0.f, 0.f);
    pos.x = (ndx >=  THRESH) ? 1.f : 0.f;
    pos.y = (ndy >=  THRESH) ? 1.f : 0.f;
    pos.z = (ndz >=  THRESH) ? 1.f : 0.f;
    pos.w = (ndw >=  THRESH) ? 1.f : 0.f;
    neg.x = (-ndx >= THRESH) ? 1.f : 0.f;
    neg.y = (-ndy >= THRESH) ? 1.f : 0.f;
    neg.z = (-ndz >= THRESH) ? 1.f : 0.f;
    neg.w = (-ndw >= THRESH) ? 1.f : 0.f;

    // out index (b,t,s,f4) = ((b*T + t)*S + s)*32 + f4
    const size_t tstride = (size_t)S * 32;
    size_t obase = ((size_t)b * T * S + s) * 32 + f4;

    #pragma unroll
    for (int t = 0; t < T; t++) {
        int ph = t % 3;
        out[obase + (size_t)t * tstride] = (ph == 0) ? pos : (ph == 1) ? neg : zero;
    }
}

extern "C" void kernel_launch(void* const* d_in, const int* in_sizes, int n_in,
                              void* d_out, int out_size) {
    const float* x = (const float*)d_in[0];
    float* out = (float*)d_out;

    dim3 bt(128, 8);
    dim3 gr(32, B);
    k_acc<<<gr, bt>>>(x);
    k_inv<<<1, 1024>>>();

    int n4 = B * S * (F / 4);          // 1,048,576 float4 threads
    k_main<<<n4 / 256, 256>>>((const float4*)x, (float4*)out);
}

// round 9
// speedup vs baseline: 1.5739x; 1.0069x over previous
#include <cuda_runtime.h>
#include <math.h>

// Problem dims
#define B 8
#define S 4096
#define F 128
#define T 16
#define THRESH 0.1f
#define EPS 1e-8f

#define NCHUNK 64            // s-chunks (64 rows each)
#define TY 8                 // s-threads per block
#define RUN 8                // rows per thread (NCHUNK*TY*RUN = 4096 = S)

// Scratch: per-(b,f) double accumulators (16KB — small, so the 1-block k_inv
// read is cheap). k_inv re-zeros them for graph replays.
__device__ double g_sum[B * F];
__device__ double g_sumsq[B * F];
__device__ __align__(16) float g_inv[B * F];

// Stats pass: float4 loads, rolling prev in registers (9 loads / 8 rows).
// block (32 f4, 8 ty) = 256 threads, grid (64, 8) = 512 blocks.
__global__ void k_acc(const float4* __restrict__ x) {
    int f4 = threadIdx.x;     // 0..31
    int ty = threadIdx.y;     // 0..7
    int chunk = blockIdx.x;   // 0..63
    int b = blockIdx.y;

    int s_start = chunk * (TY * RUN) + ty * RUN;
    const float4* p = x + (size_t)b * S * 32 + (size_t)s_start * 32 + f4;

    // prepend semantics: diff[0] = 0
    float4 prev = (s_start == 0) ? p[0] : p[-32];

    float4 s1 = make_float4(0.f, 0.f, 0.f, 0.f);
    float4 s2 = make_float4(0.f, 0.f, 0.f, 0.f);
    #pragma unroll
    for (int j = 0; j < RUN; j++) {
        float4 cur = *p;
        p += 32;
        float dx = cur.x - prev.x, dy = cur.y - prev.y;
        float dz = cur.z - prev.z, dw = cur.w - prev.w;
        s1.x += dx; s1.y += dy; s1.z += dz; s1.w += dw;
        s2.x += dx * dx; s2.y += dy * dy; s2.z += dz * dz; s2.w += dw * dw;
        prev = cur;
    }

    __shared__ float4 sh1[TY][32];
    __shared__ float4 sh2[TY][32];
    sh1[ty][f4] = s1;
    sh2[ty][f4] = s2;
    __syncthreads();

    // ty==0 reduces+atomics the sums; ty==1 the sumsqs (parallel tails).
    if (ty == 0) {
        float4 t1 = make_float4(0.f, 0.f, 0.f, 0.f);
        #pragma unroll
        for (int j = 0; j < TY; j++) {
            float4 a = sh1[j][f4];
            t1.x += a.x; t1.y += a.y; t1.z += a.z; t1.w += a.w;
        }
        int idx = b * F + f4 * 4;
        atomicAdd(&g_sum[idx + 0], (double)t1.x);
        atomicAdd(&g_sum[idx + 1], (double)t1.y);
        atomicAdd(&g_sum[idx + 2], (double)t1.z);
        atomicAdd(&g_sum[idx + 3], (double)t1.w);
    } else if (ty == 1) {
        float4 t2 = make_float4(0.f, 0.f, 0.f, 0.f);
        #pragma unroll
        for (int j = 0; j < TY; j++) {
            float4 c = sh2[j][f4];
            t2.x += c.x; t2.y += c.y; t2.z += c.z; t2.w += c.w;
        }
        int idx = b * F + f4 * 4;
        atomicAdd(&g_sumsq[idx + 0], (double)t2.x);
        atomicAdd(&g_sumsq[idx + 1], (double)t2.y);
        atomicAdd(&g_sumsq[idx + 2], (double)t2.z);
        atomicAdd(&g_sumsq[idx + 3], (double)t2.w);
    }
}

__global__ void k_inv() {
    int i = blockIdx.x * blockDim.x + threadIdx.x;
    if (i < B * F) {
        double m = g_sum[i] / (double)S;
        double var = g_sumsq[i] / (double)S - m * m;
        if (var < 0.0) var = 0.0;
        float sd = (float)sqrt(var);
        g_inv[i] = 1.0f / (sd + EPS);
        // Re-zero accumulators for the next kernel_launch call / graph replay.
        g_sum[i] = 0.0;
        g_sumsq[i] = 0.0;
    }
}

// Main expansion: one float4 per thread over B*S*F/4 elements.
// 16 coalesced plain float4 stores per thread (phase pattern t%3).
// (Measured 44.9-45.2us three times — the practical write-BW wall. UNCHANGED.)
__global__ void k_main(const float4* __restrict__ x, float4* __restrict__ out) {
    int i = blockIdx.x * blockDim.x + threadIdx.x;  // 0 .. B*S*(F/4)-1
    int f4 = i & 31;            // F/4 = 32
    int s  = (i >> 5) & 4095;
    int b  = i >> 17;

    float4 cur = x[i];
    float4 prv = (s == 0) ? cur : x[i - 32];

    const float4 inv4 = *reinterpret_cast<const float4*>(&g_inv[b * F + f4 * 4]);

    float ndx = (cur.x - prv.x) * inv4.x;
    float ndy = (cur.y - prv.y) * inv4.y;
    float ndz = (cur.z - prv.z) * inv4.z;
    float ndw = (cur.w - prv.w) * inv4.w;

    float4 pos, neg;
    const float4 zero = make_float4(0.f, 0.f, 0.f, 0.f);
    pos.x = (ndx >=  THRESH) ? 1.f : 0.f;
    pos.y = (ndy >=  THRESH) ? 1.f : 0.f;
    pos.z = (ndz >=  THRESH) ? 1.f : 0.f;
    pos.w = (ndw >=  THRESH) ? 1.f : 0.f;
    neg.x = (-ndx >= THRESH) ? 1.f : 0.f;
    neg.y = (-ndy >= THRESH) ? 1.f : 0.f;
    neg.z = (-ndz >= THRESH) ? 1.f : 0.f;
    neg.w = (-ndw >= THRESH) ? 1.f : 0.f;

    // out index (b,t,s,f4) = ((b*T + t)*S + s)*32 + f4
    const size_t tstride = (size_t)S * 32;
    size_t obase = ((size_t)b * T * S + s) * 32 + f4;

    #pragma unroll
    for (int t = 0; t < T; t++) {
        int ph = t % 3;
        out[obase + (size_t)t * tstride] = (ph == 0) ? pos : (ph == 1) ? neg : zero;
    }
}

extern "C" void kernel_launch(void* const* d_in, const int* in_sizes, int n_in,
                              void* d_out, int out_size) {
    const float* x = (const float*)d_in[0];
    float* out = (float*)d_out;

    dim3 bt(32, TY);
    dim3 gr(NCHUNK, B);
    k_acc<<<gr, bt>>>((const float4*)x);
    k_inv<<<1, 1024>>>();

    int n4 = B * S * (F / 4);          // 1,048,576 float4 threads
    k_main<<<n4 / 256, 256>>>((const float4*)x, (float4*)out);
}

// round 10
// speedup vs baseline: 1.6294x; 1.0352x over previous
#include <cuda_runtime.h>
#include <math.h>

// Problem dims
#define B 8
#define S 4096
#define F 128
#define T 16
#define THRESH 0.1f
#define EPS 1e-8f

// Stats tiling (R9 shape — measured equivalent to all other shapes)
#define NCHUNK 64
#define TY 8
#define RUN 8
#define STATS_BLOCKS (NCHUNK * B)        // 512

// Zero-slice writer: t in {2,5,8,11,14} for each b -> 40 slices of 131072 f4.
// 2048 float4 (32KB) per block -> 64 blocks/slice -> 2560 blocks.
#define F4_PER_SLICE (S * (F / 4))       // 131072
#define ZBLK_F4 2048
#define ZBLKS_PER_SLICE (F4_PER_SLICE / ZBLK_F4)   // 64
#define NZSLICES (B * 5)                 // 40
#define ZERO_BLOCKS (NZSLICES * ZBLKS_PER_SLICE)   // 2560
#define TOTAL_BLOCKS (STATS_BLOCKS + ZERO_BLOCKS)  // 3072

// Scratch: per-(b,f) double accumulators (16KB). k_inv re-zeros for replays.
__device__ double g_sum[B * F];
__device__ double g_sumsq[B * F];
__device__ __align__(16) float g_inv[B * F];

// Fused prologue: blocks [0,512) compute diff stats (atomics into g_sum/sumsq);
// blocks [512,3072) write the stat-independent zero t-slices of the output.
// The zero half keeps DRAM busy while the stats half sits in load latency.
__global__ void k_pre(const float4* __restrict__ x, float4* __restrict__ out) {
    int f4 = threadIdx.x;     // 0..31
    int ty = threadIdx.y;     // 0..7
    int tid = ty * 32 + f4;   // 0..255
    int bid = blockIdx.x;

    if (bid >= STATS_BLOCKS) {
        // ---- zero-writer half ----
        int z = bid - STATS_BLOCKS;              // 0..2559
        int slice = z >> 6;                      // /64: 0..39
        int off = (z & 63) * ZBLK_F4;
        int b = slice / 5;
        int t = 2 + 3 * (slice % 5);             // 2,5,8,11,14
        float4* dst = out + ((size_t)(b * T + t) * F4_PER_SLICE) + off + tid;
        const float4 zero = make_float4(0.f, 0.f, 0.f, 0.f);
        #pragma unroll
        for (int k = 0; k < ZBLK_F4 / 256; k++)  // 8 stores, 256-f4 stride
            dst[k * 256] = zero;
        return;
    }

    // ---- stats half (R9 k_acc, unchanged) ----
    int chunk = bid & (NCHUNK - 1);
    int b = bid >> 6;

    int s_start = chunk * (TY * RUN) + ty * RUN;
    const float4* p = x + (size_t)b * S * 32 + (size_t)s_start * 32 + f4;

    float4 prev = (s_start == 0) ? p[0] : p[-32];   // prepend: diff[0] = 0

    float4 s1 = make_float4(0.f, 0.f, 0.f, 0.f);
    float4 s2 = make_float4(0.f, 0.f, 0.f, 0.f);
    #pragma unroll
    for (int j = 0; j < RUN; j++) {
        float4 cur = *p;
        p += 32;
        float dx = cur.x - prev.x, dy = cur.y - prev.y;
        float dz = cur.z - prev.z, dw = cur.w - prev.w;
        s1.x += dx; s1.y += dy; s1.z += dz; s1.w += dw;
        s2.x += dx * dx; s2.y += dy * dy; s2.z += dz * dz; s2.w += dw * dw;
        prev = cur;
    }

    __shared__ float4 sh1[TY][32];
    __shared__ float4 sh2[TY][32];
    sh1[ty][f4] = s1;
    sh2[ty][f4] = s2;
    __syncthreads();

    if (ty == 0) {
        float4 t1 = make_float4(0.f, 0.f, 0.f, 0.f);
        #pragma unroll
        for (int j = 0; j < TY; j++) {
            float4 a = sh1[j][f4];
            t1.x += a.x; t1.y += a.y; t1.z += a.z; t1.w += a.w;
        }
        int idx = b * F + f4 * 4;
        atomicAdd(&g_sum[idx + 0], (double)t1.x);
        atomicAdd(&g_sum[idx + 1], (double)t1.y);
        atomicAdd(&g_sum[idx + 2], (double)t1.z);
        atomicAdd(&g_sum[idx + 3], (double)t1.w);
    } else if (ty == 1) {
        float4 t2 = make_float4(0.f, 0.f, 0.f, 0.f);
        #pragma unroll
        for (int j = 0; j < TY; j++) {
            float4 c = sh2[j][f4];
            t2.x += c.x; t2.y += c.y; t2.z += c.z; t2.w += c.w;
        }
        int idx = b * F + f4 * 4;
        atomicAdd(&g_sumsq[idx + 0], (double)t2.x);
        atomicAdd(&g_sumsq[idx + 1], (double)t2.y);
        atomicAdd(&g_sumsq[idx + 2], (double)t2.z);
        atomicAdd(&g_sumsq[idx + 3], (double)t2.w);
    }
}

__global__ void k_inv() {
    int i = blockIdx.x * blockDim.x + threadIdx.x;
    if (i < B * F) {
        double m = g_sum[i] / (double)S;
        double var = g_sumsq[i] / (double)S - m * m;
        if (var < 0.0) var = 0.0;
        float sd = (float)sqrt(var);
        g_inv[i] = 1.0f / (sd + EPS);
        g_sum[i] = 0.0;     // re-zero for next call / graph replay
        g_sumsq[i] = 0.0;
    }
}

// Pos/neg expansion: like the verified k_main but skips the zero slices
// (already written by k_pre). 11 stores per thread instead of 16.
__global__ void k_main_pn(const float4* __restrict__ x, float4* __restrict__ out) {
    int i = blockIdx.x * blockDim.x + threadIdx.x;  // 0 .. B*S*(F/4)-1
    int f4 = i & 31;
    int s  = (i >> 5) & 4095;
    int b  = i >> 17;

    float4 cur = x[i];
    float4 prv = (s == 0) ? cur : x[i - 32];

    const float4 inv4 = *reinterpret_cast<const float4*>(&g_inv[b * F + f4 * 4]);

    float ndx = (cur.x - prv.x) * inv4.x;
    float ndy = (cur.y - prv.y) * inv4.y;
    float ndz = (cur.z - prv.z) * inv4.z;
    float ndw = (cur.w - prv.w) * inv4.w;

    float4 pos, neg;
    pos.x = (ndx >=  THRESH) ? 1.f : 0.f;
    pos.y = (ndy >=  THRESH) ? 1.f : 0.f;
    pos.z = (ndz >=  THRESH) ? 1.f : 0.f;
    pos.w = (ndw >=  THRESH) ? 1.f : 0.f;
    neg.x = (-ndx >= THRESH) ? 1.f : 0.f;
    neg.y = (-ndy >= THRESH) ? 1.f : 0.f;
    neg.z = (-ndz >= THRESH) ? 1.f : 0.f;
    neg.w = (-ndw >= THRESH) ? 1.f : 0.f;

    const size_t tstride = (size_t)S * 32;
    size_t obase = ((size_t)b * T * S + s) * 32 + f4;

    #pragma unroll
    for (int t = 0; t < T; t++) {
        int ph = t % 3;
        if (ph == 2) continue;                      // zeros already written
        out[obase + (size_t)t * tstride] = (ph == 0) ? pos : neg;
    }
}

extern "C" void kernel_launch(void* const* d_in, const int* in_sizes, int n_in,
                              void* d_out, int out_size) {
    const float* x = (const float*)d_in[0];
    float* out = (float*)d_out;

    dim3 bt(32, TY);
    k_pre<<<TOTAL_BLOCKS, bt>>>((const float4*)x, (float4*)out);
    k_inv<<<1, 1024>>>();

    int n4 = B * S * (F / 4);          // 1,048,576 float4 threads
    k_main_pn<<<n4 / 256, 256>>>((const float4*)x, (float4*)out);
}